// round 1
// baseline (speedup 1.0000x reference)
#include <cuda_runtime.h>
#include <math.h>
#include <stdint.h>

// ---------------- problem sizes ----------------
#define NA 50000
#define NP 100000
#define HC 128
#define NH 8
#define HD 16
#define EW 400000
#define ER 400000
#define EC 800000
#define BN_EPS 1e-5f

// ---------------- scratch layout (floats) ----------------
#define OFF_XA    0ull
#define OFF_XP    (OFF_XA   + (size_t)NA*HC)          // 6.4M
#define OFF_KQVA  (OFF_XP   + (size_t)NP*HC)          // 19.2M
#define OFF_KQVP  (OFF_KQVA + (size_t)NA*384)
#define OFF_KE0   (OFF_KQVP + (size_t)NP*384)
#define OFF_VE0   (OFF_KE0  + (size_t)NA*HC)
#define OFF_KE1   (OFF_VE0  + (size_t)NA*HC)
#define OFF_VE1   (OFF_KE1  + (size_t)NP*HC)
#define OFF_KE2   (OFF_VE1  + (size_t)NP*HC)
#define OFF_VE2   (OFF_KE2  + (size_t)NP*HC)
#define OFF_AL0   (OFF_VE2  + (size_t)NP*HC)
#define OFF_AL1   (OFF_AL0  + (size_t)EW*NH)
#define OFF_AL2   (OFF_AL1  + (size_t)ER*NH)
#define OFF_MA    (OFF_AL2  + (size_t)EC*NH)
#define OFF_SA    (OFF_MA   + (size_t)NA*NH)
#define OFF_MP    (OFF_SA   + (size_t)NA*NH)
#define OFF_SP    (OFF_MP   + (size_t)NP*NH)
#define OFF_AGGA  (OFF_SP   + (size_t)NP*NH)
#define OFF_AGGP  (OFF_AGGA + (size_t)NA*HC)
#define OFF_TMPA  (OFF_AGGP + (size_t)NP*HC)
#define OFF_TMPP  (OFF_TMPA + (size_t)NA*HC)
#define OFF_STATS (OFF_TMPP + (size_t)NP*HC)
#define TOTAL_FLOATS (OFF_STATS + 512ull)

__device__ float g_scratch[TOTAL_FLOATS];

// ---------------- GEMM: C[M,N] = A[M,K] @ W[K,N] + bias, optional relu ----
// BM=128, BN=64, BK=16, 16x16 threads, 8x4 per-thread micro-tile.
__global__ void gemm_bias_act(const float* __restrict__ A, const float* __restrict__ W,
                              const float* __restrict__ bias, float* __restrict__ C,
                              int M, int N, int K, int act)
{
    __shared__ float As[16][128];
    __shared__ float Bs[16][64];
    const int bm = blockIdx.y * 128;
    const int bn = blockIdx.x * 64;
    const int tid = threadIdx.y * 16 + threadIdx.x;
    float acc[8][4];
#pragma unroll
    for (int i = 0; i < 8; i++)
#pragma unroll
        for (int j = 0; j < 4; j++) acc[i][j] = 0.f;

    for (int k0 = 0; k0 < K; k0 += 16) {
        // A tile: 128 rows x 16 k
#pragma unroll
        for (int i = 0; i < 2; i++) {
            int id  = tid + i * 256;        // 0..511
            int row = id >> 2;
            int kc  = (id & 3) * 4;
            int grow = bm + row;
            float4 v = make_float4(0.f, 0.f, 0.f, 0.f);
            if (grow < M) v = *(const float4*)(A + (size_t)grow * K + k0 + kc);
            As[kc + 0][row] = v.x; As[kc + 1][row] = v.y;
            As[kc + 2][row] = v.z; As[kc + 3][row] = v.w;
        }
        // B tile: 16 k x 64 n
        {
            int row = tid >> 4;
            int col = (tid & 15) * 4;
            float4 v = *(const float4*)(W + (size_t)(k0 + row) * N + bn + col);
            Bs[row][col + 0] = v.x; Bs[row][col + 1] = v.y;
            Bs[row][col + 2] = v.z; Bs[row][col + 3] = v.w;
        }
        __syncthreads();
#pragma unroll
        for (int kk = 0; kk < 16; kk++) {
            float a[8], b[4];
#pragma unroll
            for (int i = 0; i < 8; i++) a[i] = As[kk][threadIdx.y * 8 + i];
#pragma unroll
            for (int j = 0; j < 4; j++) b[j] = Bs[kk][threadIdx.x * 4 + j];
#pragma unroll
            for (int i = 0; i < 8; i++)
#pragma unroll
                for (int j = 0; j < 4; j++)
                    acc[i][j] += a[i] * b[j];
        }
        __syncthreads();
    }
#pragma unroll
    for (int i = 0; i < 8; i++) {
        int row = bm + threadIdx.y * 8 + i;
        if (row >= M) continue;
#pragma unroll
        for (int j = 0; j < 4; j++) {
            int col = bn + threadIdx.x * 4 + j;
            float v = acc[i][j] + bias[col];
            if (act == 1) v = fmaxf(v, 0.f);
            C[(size_t)row * N + col] = v;
        }
    }
}

// ------------- per-relation per-head transform: out[n,h,e] = sum_d in[n,h,d]*A[h,d,e]
// in = kqv[:,koff:koff+128] of a [N,384] buffer; A is [8,16,16]
__global__ void rel_transform(const float* __restrict__ kqv, int koff,
                              const float* __restrict__ A8,
                              float* __restrict__ out, int N)
{
    __shared__ float sA[2048];
    __shared__ float sv[128];
    for (int i = threadIdx.x; i < 2048; i += 128) sA[i] = A8[i];
    __syncthreads();
    const int h = threadIdx.x >> 4;
    const int e = threadIdx.x & 15;
    for (int n = blockIdx.x; n < N; n += gridDim.x) {
        sv[threadIdx.x] = kqv[(size_t)n * 384 + koff + threadIdx.x];
        __syncthreads();
        float acc = 0.f;
#pragma unroll
        for (int d = 0; d < 16; d++)
            acc += sv[h * 16 + d] * sA[(h * 16 + d) * 16 + e];
        out[(size_t)n * 128 + threadIdx.x] = acc;
        __syncthreads();
    }
}

// ------------- attention logits: alpha[e,h] = (q[dst,h,:] . ke[src,h,:]) * prel[h] * 0.25
__global__ void alpha_kernel(const float* __restrict__ kqv_dst, const float* __restrict__ ke,
                             const int* __restrict__ src, const int* __restrict__ dst,
                             const float* __restrict__ prel, float* __restrict__ alpha, int E)
{
    int gid = blockIdx.x * blockDim.x + threadIdx.x;
    if (gid >= E * NH) return;
    int e = gid >> 3, h = gid & 7;
    int s = src[e], d = dst[e];
    const float4* qp = (const float4*)(kqv_dst + (size_t)d * 384 + 128 + h * 16);
    const float4* kp = (const float4*)(ke + (size_t)s * 128 + h * 16);
    float acc = 0.f;
#pragma unroll
    for (int i = 0; i < 4; i++) {
        float4 a = qp[i], b = kp[i];
        acc += a.x * b.x + a.y * b.y + a.z * b.z + a.w * b.w;
    }
    alpha[gid] = acc * prel[h] * 0.25f;
}

__device__ __forceinline__ void atomicMaxFloat(float* addr, float val)
{
    if (val >= 0.f)
        atomicMax((int*)addr, __float_as_int(val));
    else
        atomicMin((unsigned int*)addr, __float_as_uint(val));
}

__global__ void seg_max(const float* __restrict__ alpha, const int* __restrict__ dst,
                        float* __restrict__ m, int E)
{
    int gid = blockIdx.x * blockDim.x + threadIdx.x;
    if (gid >= E * NH) return;
    int e = gid >> 3, h = gid & 7;
    atomicMaxFloat(&m[(size_t)dst[e] * NH + h], alpha[gid]);
}

__global__ void seg_expsum(float* __restrict__ alpha, const int* __restrict__ dst,
                           const float* __restrict__ m, float* __restrict__ ssum, int E)
{
    int gid = blockIdx.x * blockDim.x + threadIdx.x;
    if (gid >= E * NH) return;
    int e = gid >> 3, h = gid & 7;
    int d = dst[e];
    float w = expf(alpha[gid] - m[(size_t)d * NH + h]);
    alpha[gid] = w;
    atomicAdd(&ssum[(size_t)d * NH + h], w);
}

__global__ void agg_kernel(const float* __restrict__ ve, const int* __restrict__ src,
                           const int* __restrict__ dst, const float* __restrict__ alpha,
                           const float* __restrict__ ssum, float* __restrict__ agg, int E)
{
    int gid = blockIdx.x * blockDim.x + threadIdx.x;
    if (gid >= E * 128) return;
    int e = gid >> 7, c = gid & 127, h = c >> 4;
    int s = src[e], d = dst[e];
    float w = alpha[(size_t)e * NH + h] / (ssum[(size_t)d * NH + h] + 1e-16f);
    atomicAdd(&agg[(size_t)d * 128 + c], w * ve[(size_t)s * 128 + c]);
}

__global__ void gelu_inplace(float* __restrict__ p, int n)
{
    int i = blockIdx.x * blockDim.x + threadIdx.x;
    if (i >= n) return;
    float v = p[i];
    p[i] = 0.5f * v * (1.f + erff(v * 0.70710678118654752f));
}

__global__ void skip_mix(float* __restrict__ out, const float* __restrict__ xold,
                         const float* __restrict__ skipv, int n)
{
    int i = blockIdx.x * blockDim.x + threadIdx.x;
    if (i >= n) return;
    float sk = 1.f / (1.f + expf(-skipv[0]));
    out[i] = sk * out[i] + (1.f - sk) * xold[i];
}

__global__ void fill_val(float* __restrict__ p, float v, int n)
{
    int i = blockIdx.x * blockDim.x + threadIdx.x;
    if (i < n) p[i] = v;
}

// BN stats: per-channel sum and sumsq. blockDim=128, each block covers 256 rows.
__global__ void bn_stats(const float* __restrict__ h, float* __restrict__ stats, int N)
{
    int c = threadIdx.x;
    int r0 = blockIdx.x * 256;
    int r1 = min(N, r0 + 256);
    float s = 0.f, s2 = 0.f;
    for (int r = r0; r < r1; r++) {
        float v = h[(size_t)r * 128 + c];
        s += v; s2 += v * v;
    }
    atomicAdd(&stats[c], s);
    atomicAdd(&stats[128 + c], s2);
}

__global__ void bn_apply(const float* __restrict__ h, const float* __restrict__ stats,
                         const float* __restrict__ gamma, const float* __restrict__ beta,
                         float* __restrict__ out, int N)
{
    int i = blockIdx.x * blockDim.x + threadIdx.x;
    if (i >= N * 128) return;
    int c = i & 127;
    float invN = 1.f / (float)N;
    float mu = stats[c] * invN;
    float var = stats[128 + c] * invN - mu * mu;
    float v = h[i];
    out[i] = (v - mu) * rsqrtf(var + BN_EPS) * gamma[c] + beta[c];
}

// ---------------------------------------------------------------
static inline int cdiv(long long a, long long b) { return (int)((a + b - 1) / b); }

extern "C" void kernel_launch(void* const* d_in, const int* in_sizes, int n_in,
                              void* d_out, int out_size)
{
    const float* x_author = (const float*)d_in[0];
    const float* x_paper  = (const float*)d_in[1];
    const int* writes_src = (const int*)d_in[2];
    const int* writes_dst = (const int*)d_in[3];
    const int* rev_src    = (const int*)d_in[4];
    const int* rev_dst    = (const int*)d_in[5];
    const int* cites_src  = (const int*)d_in[6];
    const int* cites_dst  = (const int*)d_in[7];
    const float* linA_W   = (const float*)d_in[8];
    const float* linA_b   = (const float*)d_in[9];
    const float* linP_W   = (const float*)d_in[10];
    const float* linP_b   = (const float*)d_in[11];
    const float* kqv_W    = (const float*)d_in[12];
    const float* kqv_b    = (const float*)d_in[13];
    const float* a_k      = (const float*)d_in[14];
    const float* a_v      = (const float*)d_in[15];
    const float* p_rel    = (const float*)d_in[16];
    const float* out_W    = (const float*)d_in[17];
    const float* out_b    = (const float*)d_in[18];
    const float* skipP    = (const float*)d_in[19];
    const float* bn_gamma = (const float*)d_in[20];
    const float* bn_beta  = (const float*)d_in[21];

    float* base = nullptr;
    cudaGetSymbolAddress((void**)&base, g_scratch);

    float* XA   = base + OFF_XA;
    float* XP   = base + OFF_XP;
    float* KQVA = base + OFF_KQVA;
    float* KQVP = base + OFF_KQVP;
    float* KE0  = base + OFF_KE0;
    float* VE0  = base + OFF_VE0;
    float* KE1  = base + OFF_KE1;
    float* VE1  = base + OFF_VE1;
    float* KE2  = base + OFF_KE2;
    float* VE2  = base + OFF_VE2;
    float* AL0  = base + OFF_AL0;
    float* AL1  = base + OFF_AL1;
    float* AL2  = base + OFF_AL2;
    float* MA   = base + OFF_MA;
    float* SA   = base + OFF_SA;
    float* MP   = base + OFF_MP;
    float* SP   = base + OFF_SP;
    float* AGGA = base + OFF_AGGA;
    float* AGGP = base + OFF_AGGP;
    float* TMPA = base + OFF_TMPA;
    float* TMPP = base + OFF_TMPP;
    float* STA  = base + OFF_STATS;       // author stats [256]
    float* STP  = base + OFF_STATS + 256; // paper stats [256]

    const dim3 tb(16, 16);

    // input projections + relu
    gemm_bias_act<<<dim3(2, cdiv(NA, 128)), tb>>>(x_author, linA_W, linA_b, XA, NA, 128, 128, 1);
    gemm_bias_act<<<dim3(2, cdiv(NP, 128)), tb>>>(x_paper,  linP_W, linP_b, XP, NP, 128, 128, 1);

    for (int l = 0; l < 2; l++) {
        // KQV GEMMs (N=384)
        gemm_bias_act<<<dim3(6, cdiv(NA, 128)), tb>>>(XA, kqv_W + (size_t)(l * 2 + 0) * 128 * 384,
                                                      kqv_b + (size_t)(l * 2 + 0) * 384, KQVA, NA, 384, 128, 0);
        gemm_bias_act<<<dim3(6, cdiv(NP, 128)), tb>>>(XP, kqv_W + (size_t)(l * 2 + 1) * 128 * 384,
                                                      kqv_b + (size_t)(l * 2 + 1) * 384, KQVP, NP, 384, 128, 0);

        // per-relation K/V transforms (on source nodes)
        rel_transform<<<2048, 128>>>(KQVA, 0,   a_k + (size_t)(l * 3 + 0) * 2048, KE0, NA);
        rel_transform<<<2048, 128>>>(KQVA, 256, a_v + (size_t)(l * 3 + 0) * 2048, VE0, NA);
        rel_transform<<<2048, 128>>>(KQVP, 0,   a_k + (size_t)(l * 3 + 1) * 2048, KE1, NP);
        rel_transform<<<2048, 128>>>(KQVP, 256, a_v + (size_t)(l * 3 + 1) * 2048, VE1, NP);
        rel_transform<<<2048, 128>>>(KQVP, 0,   a_k + (size_t)(l * 3 + 2) * 2048, KE2, NP);
        rel_transform<<<2048, 128>>>(KQVP, 256, a_v + (size_t)(l * 3 + 2) * 2048, VE2, NP);

        // attention logits
        alpha_kernel<<<cdiv((long long)EW * NH, 256), 256>>>(KQVP, KE0, writes_src, writes_dst,
                                                             p_rel + (size_t)(l * 3 + 0) * NH, AL0, EW);
        alpha_kernel<<<cdiv((long long)ER * NH, 256), 256>>>(KQVA, KE1, rev_src, rev_dst,
                                                             p_rel + (size_t)(l * 3 + 1) * NH, AL1, ER);
        alpha_kernel<<<cdiv((long long)EC * NH, 256), 256>>>(KQVP, KE2, cites_src, cites_dst,
                                                             p_rel + (size_t)(l * 3 + 2) * NH, AL2, EC);

        // reset segment buffers
        fill_val<<<cdiv(NA * NH, 256), 256>>>(MA, -INFINITY, NA * NH);
        fill_val<<<cdiv(NP * NH, 256), 256>>>(MP, -INFINITY, NP * NH);
        cudaMemsetAsync(SA, 0, (size_t)NA * NH * 4, 0);
        cudaMemsetAsync(SP, 0, (size_t)NP * NH * 4, 0);
        cudaMemsetAsync(AGGA, 0, (size_t)NA * 128 * 4, 0);
        cudaMemsetAsync(AGGP, 0, (size_t)NP * 128 * 4, 0);

        // segment softmax: max
        seg_max<<<cdiv((long long)EW * NH, 256), 256>>>(AL0, writes_dst, MP, EW);
        seg_max<<<cdiv((long long)ER * NH, 256), 256>>>(AL1, rev_dst,    MA, ER);
        seg_max<<<cdiv((long long)EC * NH, 256), 256>>>(AL2, cites_dst,  MP, EC);
        // exp + sum
        seg_expsum<<<cdiv((long long)EW * NH, 256), 256>>>(AL0, writes_dst, MP, SP, EW);
        seg_expsum<<<cdiv((long long)ER * NH, 256), 256>>>(AL1, rev_dst,    MA, SA, ER);
        seg_expsum<<<cdiv((long long)EC * NH, 256), 256>>>(AL2, cites_dst,  MP, SP, EC);
        // weighted aggregate
        agg_kernel<<<cdiv((long long)EW * 128, 256), 256>>>(VE0, writes_src, writes_dst, AL0, SP, AGGP, EW);
        agg_kernel<<<cdiv((long long)ER * 128, 256), 256>>>(VE1, rev_src,    rev_dst,    AL1, SA, AGGA, ER);
        agg_kernel<<<cdiv((long long)EC * 128, 256), 256>>>(VE2, cites_src,  cites_dst,  AL2, SP, AGGP, EC);

        // gelu
        gelu_inplace<<<cdiv((long long)NA * 128, 256), 256>>>(AGGA, NA * 128);
        gelu_inplace<<<cdiv((long long)NP * 128, 256), 256>>>(AGGP, NP * 128);

        // output projection
        gemm_bias_act<<<dim3(2, cdiv(NA, 128)), tb>>>(AGGA, out_W + (size_t)(l * 2 + 0) * 128 * 128,
                                                      out_b + (size_t)(l * 2 + 0) * 128, TMPA, NA, 128, 128, 0);
        gemm_bias_act<<<dim3(2, cdiv(NP, 128)), tb>>>(AGGP, out_W + (size_t)(l * 2 + 1) * 128 * 128,
                                                      out_b + (size_t)(l * 2 + 1) * 128, TMPP, NP, 128, 128, 0);

        // skip mix
        skip_mix<<<cdiv((long long)NA * 128, 256), 256>>>(TMPA, XA, skipP + (l * 2 + 0), NA * 128);
        skip_mix<<<cdiv((long long)NP * 128, 256), 256>>>(TMPP, XP, skipP + (l * 2 + 1), NP * 128);

        // batch norm (training-mode stats), per node type
        cudaMemsetAsync(STA, 0, 512 * 4, 0);
        bn_stats<<<cdiv(NA, 256), 128>>>(TMPA, STA, NA);
        bn_stats<<<cdiv(NP, 256), 128>>>(TMPP, STP, NP);
        bn_apply<<<cdiv((long long)NA * 128, 256), 256>>>(TMPA, STA, bn_gamma + (size_t)l * 128,
                                                          bn_beta + (size_t)l * 128, XA, NA);
        bn_apply<<<cdiv((long long)NP * 128, 256), 256>>>(TMPP, STP, bn_gamma + (size_t)l * 128,
                                                          bn_beta + (size_t)l * 128, XP, NP);
    }

    // output: (author, paper) concatenated
    cudaMemcpyAsync(d_out, XA, (size_t)NA * 128 * 4, cudaMemcpyDeviceToDevice, 0);
    cudaMemcpyAsync((float*)d_out + (size_t)NA * 128, XP, (size_t)NP * 128 * 4,
                    cudaMemcpyDeviceToDevice, 0);
}

// round 2
// speedup vs baseline: 1.6582x; 1.6582x over previous
#include <cuda_runtime.h>
#include <math.h>
#include <stdint.h>

// ---------------- problem sizes ----------------
#define NA 50000
#define NP 100000
#define HC 128
#define NH 8
#define EW 400000
#define ER 400000
#define EC 800000
#define EP (EW + EC)
#define BN_EPS 1e-5f

// ---------------- scratch layout (floats) ----------------
#define OFF_XA    0ull
#define OFF_XP    (OFF_XA   + (size_t)NA*128)
#define OFF_KQVA  (OFF_XP   + (size_t)NP*128)
#define OFF_KQVP  (OFF_KQVA + (size_t)NA*384)
#define OFF_KEP   (OFF_KQVP + (size_t)NP*384)        // [(NA+NP),128]
#define OFF_VEP   (OFF_KEP  + (size_t)(NA+NP)*128)
#define OFF_KEA   (OFF_VEP  + (size_t)(NA+NP)*128)   // [NP,128]
#define OFF_VEA   (OFF_KEA  + (size_t)NP*128)
#define OFF_AGGA  (OFF_VEA  + (size_t)NP*128)
#define OFF_AGGP  (OFF_AGGA + (size_t)NA*128)
#define OFF_TMPA  (OFF_AGGP + (size_t)NP*128)
#define OFF_TMPP  (OFF_TMPA + (size_t)NA*128)
#define OFF_STATS (OFF_TMPP + (size_t)NP*128)
// integer region (reinterpreted as int*)
#define OFF_INT   (OFF_STATS + 512ull)
#define IOFF_ROWP 0ull                         // NP+1
#define IOFF_ROWA (IOFF_ROWP + NP + 1)         // NA+1
#define IOFF_CURP (IOFF_ROWA + NA + 1)         // NP
#define IOFF_CURA (IOFF_CURP + NP)             // NA
#define IOFF_SRCP (IOFF_CURA + NA)             // EP
#define IOFF_SRCA (IOFF_SRCP + EP)             // ER
#define INT_TOTAL (IOFF_SRCA + ER)
#define TOTAL_FLOATS (OFF_INT + INT_TOTAL + 64ull)

__device__ float g_scratch[TOTAL_FLOATS];

// ---------------- GEMM: C[M,N] = A[M,K] @ W[K,N] + bias ----
// act: 0=none, 1=relu, 2=skip-mix (v = sk*v + (1-sk)*xold)
__global__ void gemm_bias_act(const float* __restrict__ A, const float* __restrict__ W,
                              const float* __restrict__ bias, float* __restrict__ C,
                              int M, int N, int K, int act,
                              const float* __restrict__ xold, const float* __restrict__ skipv)
{
    __shared__ float As[16][128];
    __shared__ float Bs[16][64];
    const int bm = blockIdx.y * 128;
    const int bn = blockIdx.x * 64;
    const int tid = threadIdx.y * 16 + threadIdx.x;
    float acc[8][4];
#pragma unroll
    for (int i = 0; i < 8; i++)
#pragma unroll
        for (int j = 0; j < 4; j++) acc[i][j] = 0.f;

    for (int k0 = 0; k0 < K; k0 += 16) {
#pragma unroll
        for (int i = 0; i < 2; i++) {
            int id  = tid + i * 256;
            int row = id >> 2;
            int kc  = (id & 3) * 4;
            int grow = bm + row;
            float4 v = make_float4(0.f, 0.f, 0.f, 0.f);
            if (grow < M) v = *(const float4*)(A + (size_t)grow * K + k0 + kc);
            As[kc + 0][row] = v.x; As[kc + 1][row] = v.y;
            As[kc + 2][row] = v.z; As[kc + 3][row] = v.w;
        }
        {
            int row = tid >> 4;
            int col = (tid & 15) * 4;
            float4 v = *(const float4*)(W + (size_t)(k0 + row) * N + bn + col);
            Bs[row][col + 0] = v.x; Bs[row][col + 1] = v.y;
            Bs[row][col + 2] = v.z; Bs[row][col + 3] = v.w;
        }
        __syncthreads();
#pragma unroll
        for (int kk = 0; kk < 16; kk++) {
            float a[8], b[4];
#pragma unroll
            for (int i = 0; i < 8; i++) a[i] = As[kk][threadIdx.y * 8 + i];
#pragma unroll
            for (int j = 0; j < 4; j++) b[j] = Bs[kk][threadIdx.x * 4 + j];
#pragma unroll
            for (int i = 0; i < 8; i++)
#pragma unroll
                for (int j = 0; j < 4; j++)
                    acc[i][j] += a[i] * b[j];
        }
        __syncthreads();
    }
    float sk = 0.f;
    if (act == 2) sk = 1.f / (1.f + __expf(-skipv[0]));
#pragma unroll
    for (int i = 0; i < 8; i++) {
        int row = bm + threadIdx.y * 8 + i;
        if (row >= M) continue;
#pragma unroll
        for (int j = 0; j < 4; j++) {
            int col = bn + threadIdx.x * 4 + j;
            float v = acc[i][j] + bias[col];
            if (act == 1) v = fmaxf(v, 0.f);
            else if (act == 2) v = sk * v + (1.f - sk) * xold[(size_t)row * N + col];
            C[(size_t)row * N + col] = v;
        }
    }
}

// ------------- per-relation per-head transform: out[n,h,e] = sum_d in[n,h,d]*A[h,d,e]
__global__ void rel_transform(const float* __restrict__ kqv, int koff,
                              const float* __restrict__ A8,
                              float* __restrict__ out, int N)
{
    __shared__ float sA[2048];
    __shared__ float sv[128];
    for (int i = threadIdx.x; i < 2048; i += 128) sA[i] = A8[i];
    __syncthreads();
    const int h = threadIdx.x >> 4;
    const int e = threadIdx.x & 15;
    for (int n = blockIdx.x; n < N; n += gridDim.x) {
        sv[threadIdx.x] = kqv[(size_t)n * 384 + koff + threadIdx.x];
        __syncthreads();
        float acc = 0.f;
#pragma unroll
        for (int d = 0; d < 16; d++)
            acc += sv[h * 16 + d] * sA[(h * 16 + d) * 16 + e];
        out[(size_t)n * 128 + threadIdx.x] = acc;
        __syncthreads();
    }
}

// ---------------- CSR build ----------------
__global__ void hist_kernel(const int* __restrict__ dst, int* __restrict__ deg, int E)
{
    int i = blockIdx.x * blockDim.x + threadIdx.x;
    if (i < E) atomicAdd(&deg[dst[i]], 1);
}

// single-block exclusive scan (also writes row[n] = total)
__global__ void scan_excl(int* __restrict__ deg_inout_row, const int* __restrict__ deg, int n)
{
    __shared__ int sdata[1024];
    __shared__ int carry_s;
    if (threadIdx.x == 0) carry_s = 0;
    __syncthreads();
    for (int base = 0; base < n; base += 1024) {
        int i = base + threadIdx.x;
        int v = (i < n) ? deg[i] : 0;
        sdata[threadIdx.x] = v;
        __syncthreads();
        for (int off = 1; off < 1024; off <<= 1) {
            int t = (threadIdx.x >= off) ? sdata[threadIdx.x - off] : 0;
            __syncthreads();
            sdata[threadIdx.x] += t;
            __syncthreads();
        }
        if (i < n) deg_inout_row[i] = carry_s + sdata[threadIdx.x] - v;
        __syncthreads();
        if (threadIdx.x == 0) carry_s += sdata[1023];
        __syncthreads();
    }
    if (threadIdx.x == 0) deg_inout_row[n] = carry_s;
}

__global__ void copy_int(const int* __restrict__ src, int* __restrict__ dst, int n)
{
    int i = blockIdx.x * blockDim.x + threadIdx.x;
    if (i < n) dst[i] = src[i];
}

__global__ void scatter_kernel(const int* __restrict__ src, const int* __restrict__ dst,
                               int* __restrict__ cursor, int* __restrict__ out,
                               int E, int srcOffset)
{
    int i = blockIdx.x * blockDim.x + threadIdx.x;
    if (i >= E) return;
    int p = atomicAdd(&cursor[dst[i]], 1);
    out[p] = src[i] + srcOffset;
}

// ---------------- fused attention + softmax + aggregate + gelu ----------------
// warp per destination node. lane = h*4 + q; channel c = h*16 + q*4.
__global__ void attn_agg(const float* __restrict__ kqv, const float* __restrict__ KE,
                         const float* __restrict__ VE,
                         const int* __restrict__ rowptr, const int* __restrict__ srccol,
                         const float* __restrict__ prelA, const float* __restrict__ prelB,
                         int relBoundary, float* __restrict__ agg, int N)
{
    int warp = (blockIdx.x * blockDim.x + threadIdx.x) >> 5;
    int lane = threadIdx.x & 31;
    if (warp >= N) return;
    int h = lane >> 2;
    int c = h * 16 + (lane & 3) * 4;
    float4 q4 = *(const float4*)(kqv + (size_t)warp * 384 + 128 + c);
    float pA = prelA[h] * 0.25f;
    float pB = prelB[h] * 0.25f;
    int js = rowptr[warp], je = rowptr[warp + 1];
    float m = -INFINITY, s = 0.f;
    float4 acc = make_float4(0.f, 0.f, 0.f, 0.f);
    for (int j = js; j < je; j++) {
        int sr = srccol[j];
        float4 k4 = *(const float4*)(KE + (size_t)sr * 128 + c);
        float part = q4.x * k4.x + q4.y * k4.y + q4.z * k4.z + q4.w * k4.w;
        part += __shfl_xor_sync(0xffffffffu, part, 1);
        part += __shfl_xor_sync(0xffffffffu, part, 2);
        float a = part * ((sr >= relBoundary) ? pB : pA);
        float newm = fmaxf(m, a);
        float scl = __expf(m - newm);
        float w = __expf(a - newm);
        s = s * scl + w;
        float4 v4 = *(const float4*)(VE + (size_t)sr * 128 + c);
        acc.x = acc.x * scl + w * v4.x;
        acc.y = acc.y * scl + w * v4.y;
        acc.z = acc.z * scl + w * v4.z;
        acc.w = acc.w * scl + w * v4.w;
        m = newm;
    }
    float inv = 1.f / (s + 1e-16f);
    float4 r;
    float v;
    v = acc.x * inv; r.x = 0.5f * v * (1.f + erff(v * 0.70710678118654752f));
    v = acc.y * inv; r.y = 0.5f * v * (1.f + erff(v * 0.70710678118654752f));
    v = acc.z * inv; r.z = 0.5f * v * (1.f + erff(v * 0.70710678118654752f));
    v = acc.w * inv; r.w = 0.5f * v * (1.f + erff(v * 0.70710678118654752f));
    *(float4*)(agg + (size_t)warp * 128 + c) = r;
}

// ---------------- BatchNorm ----------------
__global__ void bn_stats(const float* __restrict__ h, float* __restrict__ stats, int N)
{
    int c = threadIdx.x;
    int r0 = blockIdx.x * 256;
    int r1 = min(N, r0 + 256);
    float s = 0.f, s2 = 0.f;
    for (int r = r0; r < r1; r++) {
        float v = h[(size_t)r * 128 + c];
        s += v; s2 += v * v;
    }
    atomicAdd(&stats[c], s);
    atomicAdd(&stats[128 + c], s2);
}

__global__ void bn_apply(const float* __restrict__ h, const float* __restrict__ stats,
                         const float* __restrict__ gamma, const float* __restrict__ beta,
                         float* __restrict__ out, int N)
{
    int i = blockIdx.x * blockDim.x + threadIdx.x;
    if (i >= N * 128) return;
    int c = i & 127;
    float invN = 1.f / (float)N;
    float mu = stats[c] * invN;
    float var = stats[128 + c] * invN - mu * mu;
    float v = h[i];
    out[i] = (v - mu) * rsqrtf(var + BN_EPS) * gamma[c] + beta[c];
}

// ---------------------------------------------------------------
static inline int cdiv(long long a, long long b) { return (int)((a + b - 1) / b); }

extern "C" void kernel_launch(void* const* d_in, const int* in_sizes, int n_in,
                              void* d_out, int out_size)
{
    const float* x_author = (const float*)d_in[0];
    const float* x_paper  = (const float*)d_in[1];
    const int* writes_src = (const int*)d_in[2];
    const int* writes_dst = (const int*)d_in[3];
    const int* rev_src    = (const int*)d_in[4];
    const int* rev_dst    = (const int*)d_in[5];
    const int* cites_src  = (const int*)d_in[6];
    const int* cites_dst  = (const int*)d_in[7];
    const float* linA_W   = (const float*)d_in[8];
    const float* linA_b   = (const float*)d_in[9];
    const float* linP_W   = (const float*)d_in[10];
    const float* linP_b   = (const float*)d_in[11];
    const float* kqv_W    = (const float*)d_in[12];
    const float* kqv_b    = (const float*)d_in[13];
    const float* a_k      = (const float*)d_in[14];
    const float* a_v      = (const float*)d_in[15];
    const float* p_rel    = (const float*)d_in[16];
    const float* out_W    = (const float*)d_in[17];
    const float* out_b    = (const float*)d_in[18];
    const float* skipP    = (const float*)d_in[19];
    const float* bn_gamma = (const float*)d_in[20];
    const float* bn_beta  = (const float*)d_in[21];

    float* base = nullptr;
    cudaGetSymbolAddress((void**)&base, g_scratch);

    float* XA   = base + OFF_XA;
    float* XP   = base + OFF_XP;
    float* KQVA = base + OFF_KQVA;
    float* KQVP = base + OFF_KQVP;
    float* KEP  = base + OFF_KEP;
    float* VEP  = base + OFF_VEP;
    float* KEA  = base + OFF_KEA;
    float* VEA  = base + OFF_VEA;
    float* AGGA = base + OFF_AGGA;
    float* AGGP = base + OFF_AGGP;
    float* TMPA = base + OFF_TMPA;
    float* TMPP = base + OFF_TMPP;
    float* STA  = base + OFF_STATS;
    float* STP  = base + OFF_STATS + 256;
    int* ibase  = (int*)(base + OFF_INT);
    int* ROWP   = ibase + IOFF_ROWP;
    int* ROWA   = ibase + IOFF_ROWA;
    int* CURP   = ibase + IOFF_CURP;
    int* CURA   = ibase + IOFF_CURA;
    int* SRCP   = ibase + IOFF_SRCP;
    int* SRCA   = ibase + IOFF_SRCA;

    const dim3 tb(16, 16);

    // -------- CSR build (once per launch; shared by both layers) --------
    // reuse CURP/CURA as degree buffers first
    cudaMemsetAsync(CURP, 0, (size_t)NP * 4, 0);
    cudaMemsetAsync(CURA, 0, (size_t)NA * 4, 0);
    hist_kernel<<<cdiv(EW, 256), 256>>>(writes_dst, CURP, EW);
    hist_kernel<<<cdiv(EC, 256), 256>>>(cites_dst, CURP, EC);
    hist_kernel<<<cdiv(ER, 256), 256>>>(rev_dst, CURA, ER);
    scan_excl<<<1, 1024>>>(ROWP, CURP, NP);
    scan_excl<<<1, 1024>>>(ROWA, CURA, NA);
    copy_int<<<cdiv(NP, 256), 256>>>(ROWP, CURP, NP);
    copy_int<<<cdiv(NA, 256), 256>>>(ROWA, CURA, NA);
    scatter_kernel<<<cdiv(EW, 256), 256>>>(writes_src, writes_dst, CURP, SRCP, EW, 0);
    scatter_kernel<<<cdiv(EC, 256), 256>>>(cites_src, cites_dst, CURP, SRCP, EC, NA);
    scatter_kernel<<<cdiv(ER, 256), 256>>>(rev_src, rev_dst, CURA, SRCA, ER, 0);

    // -------- input projections + relu --------
    gemm_bias_act<<<dim3(2, cdiv(NA, 128)), tb>>>(x_author, linA_W, linA_b, XA, NA, 128, 128, 1, nullptr, nullptr);
    gemm_bias_act<<<dim3(2, cdiv(NP, 128)), tb>>>(x_paper,  linP_W, linP_b, XP, NP, 128, 128, 1, nullptr, nullptr);

    for (int l = 0; l < 2; l++) {
        // KQV GEMMs
        gemm_bias_act<<<dim3(6, cdiv(NA, 128)), tb>>>(XA, kqv_W + (size_t)(l * 2 + 0) * 128 * 384,
                                                      kqv_b + (size_t)(l * 2 + 0) * 384, KQVA, NA, 384, 128, 0, nullptr, nullptr);
        gemm_bias_act<<<dim3(6, cdiv(NP, 128)), tb>>>(XP, kqv_W + (size_t)(l * 2 + 1) * 128 * 384,
                                                      kqv_b + (size_t)(l * 2 + 1) * 384, KQVP, NP, 384, 128, 0, nullptr, nullptr);

        // per-relation K/V transforms into combined source tables
        // paper-destined: rel0 (writes, author src) rows [0,NA), rel2 (cites, paper src) rows [NA,NA+NP)
        rel_transform<<<2048, 128>>>(KQVA, 0,   a_k + (size_t)(l * 3 + 0) * 2048, KEP, NA);
        rel_transform<<<2048, 128>>>(KQVA, 256, a_v + (size_t)(l * 3 + 0) * 2048, VEP, NA);
        rel_transform<<<2048, 128>>>(KQVP, 0,   a_k + (size_t)(l * 3 + 2) * 2048, KEP + (size_t)NA * 128, NP);
        rel_transform<<<2048, 128>>>(KQVP, 256, a_v + (size_t)(l * 3 + 2) * 2048, VEP + (size_t)NA * 128, NP);
        // author-destined: rel1 (rev, paper src)
        rel_transform<<<2048, 128>>>(KQVP, 0,   a_k + (size_t)(l * 3 + 1) * 2048, KEA, NP);
        rel_transform<<<2048, 128>>>(KQVP, 256, a_v + (size_t)(l * 3 + 1) * 2048, VEA, NP);

        // fused attention + softmax + aggregation + gelu
        attn_agg<<<cdiv((long long)NP * 32, 256), 256>>>(KQVP, KEP, VEP, ROWP, SRCP,
                                                         p_rel + (size_t)(l * 3 + 0) * NH,
                                                         p_rel + (size_t)(l * 3 + 2) * NH,
                                                         NA, AGGP, NP);
        attn_agg<<<cdiv((long long)NA * 32, 256), 256>>>(KQVA, KEA, VEA, ROWA, SRCA,
                                                         p_rel + (size_t)(l * 3 + 1) * NH,
                                                         p_rel + (size_t)(l * 3 + 1) * NH,
                                                         NP + 1, AGGA, NA);

        // output projection + fused sigmoid-skip mix
        gemm_bias_act<<<dim3(2, cdiv(NA, 128)), tb>>>(AGGA, out_W + (size_t)(l * 2 + 0) * 128 * 128,
                                                      out_b + (size_t)(l * 2 + 0) * 128, TMPA, NA, 128, 128, 2,
                                                      XA, skipP + (l * 2 + 0));
        gemm_bias_act<<<dim3(2, cdiv(NP, 128)), tb>>>(AGGP, out_W + (size_t)(l * 2 + 1) * 128 * 128,
                                                      out_b + (size_t)(l * 2 + 1) * 128, TMPP, NP, 128, 128, 2,
                                                      XP, skipP + (l * 2 + 1));

        // batch norm (training-mode stats), per node type
        cudaMemsetAsync(STA, 0, 512 * 4, 0);
        bn_stats<<<cdiv(NA, 256), 128>>>(TMPA, STA, NA);
        bn_stats<<<cdiv(NP, 256), 128>>>(TMPP, STP, NP);
        float* outA = (l == 1) ? (float*)d_out : XA;
        float* outP = (l == 1) ? (float*)d_out + (size_t)NA * 128 : XP;
        bn_apply<<<cdiv((long long)NA * 128, 256), 256>>>(TMPA, STA, bn_gamma + (size_t)l * 128,
                                                          bn_beta + (size_t)l * 128, outA, NA);
        bn_apply<<<cdiv((long long)NP * 128, 256), 256>>>(TMPP, STP, bn_gamma + (size_t)l * 128,
                                                          bn_beta + (size_t)l * 128, outP, NP);
    }
}

// round 3
// speedup vs baseline: 1.7592x; 1.0610x over previous
#include <cuda_runtime.h>
#include <math.h>
#include <stdint.h>

// ---------------- problem sizes ----------------
#define NA 50000
#define NP 100000
#define HC 128
#define NH 8
#define EW 400000
#define ER 400000
#define EC 800000
#define EP (EW + EC)
#define BN_EPS 1e-5f

// ---------------- scratch layout (floats) ----------------
#define OFF_XA    0ull
#define OFF_XP    (OFF_XA   + (size_t)NA*128)
#define OFF_KQVA  (OFF_XP   + (size_t)NP*128)
#define OFF_KQVP  (OFF_KQVA + (size_t)NA*384)
#define OFF_KEP   (OFF_KQVP + (size_t)NP*384)        // [(NA+NP),128]
#define OFF_VEP   (OFF_KEP  + (size_t)(NA+NP)*128)
#define OFF_KEA   (OFF_VEP  + (size_t)(NA+NP)*128)   // [NP,128]
#define OFF_VEA   (OFF_KEA  + (size_t)NP*128)
#define OFF_AGGA  (OFF_VEA  + (size_t)NP*128)
#define OFF_AGGP  (OFF_AGGA + (size_t)NA*128)
#define OFF_TMPA  (OFF_AGGP + (size_t)NP*128)
#define OFF_TMPP  (OFF_TMPA + (size_t)NA*128)
#define OFF_STATS (OFF_TMPP + (size_t)NP*128)
// integer region (reinterpreted as int*)
#define OFF_INT   (OFF_STATS + 512ull)
#define IOFF_ROWP 0ull                         // NP+1
#define IOFF_ROWA (IOFF_ROWP + NP + 1)         // NA+1
#define IOFF_CURP (IOFF_ROWA + NA + 1)         // NP
#define IOFF_CURA (IOFF_CURP + NP)             // NA
#define IOFF_SRCP (IOFF_CURA + NA)             // EP
#define IOFF_SRCA (IOFF_SRCP + EP)             // ER
#define IOFF_BS   (IOFF_SRCA + ER)             // 256 (block sums)
#define INT_TOTAL (IOFF_BS + 256)
#define TOTAL_FLOATS (OFF_INT + INT_TOTAL + 64ull)

__device__ float g_scratch[TOTAL_FLOATS];

// ---------------- GEMM: C[M,N] = A[M,K] @ W[K,N] + bias ----
// 128x128 tile, BK=16, 256 threads, 8x8 micro-tile.
// act: 0=none, 1=relu, 2=skip-mix (v = sk*v + (1-sk)*xold)
__global__ void __launch_bounds__(256, 2)
gemm128(const float* __restrict__ A, const float* __restrict__ W,
        const float* __restrict__ bias, float* __restrict__ C,
        int M, int N, int K, int act,
        const float* __restrict__ xold, const float* __restrict__ skipv)
{
    __shared__ float As[16][128];
    __shared__ float Bs[16][128];
    const int bm = blockIdx.y * 128;
    const int bn = blockIdx.x * 128;
    const int tid = threadIdx.x;
    const int tx = tid & 15;
    const int ty = tid >> 4;
    float acc[8][8];
#pragma unroll
    for (int i = 0; i < 8; i++)
#pragma unroll
        for (int j = 0; j < 8; j++) acc[i][j] = 0.f;

    for (int k0 = 0; k0 < K; k0 += 16) {
        // A tile: 128 rows x 16 k (2048 floats, 2 float4 per thread)
#pragma unroll
        for (int i = 0; i < 2; i++) {
            int id  = tid + i * 256;
            int row = id >> 2;
            int kc  = (id & 3) * 4;
            int grow = bm + row;
            float4 v = make_float4(0.f, 0.f, 0.f, 0.f);
            if (grow < M) v = *(const float4*)(A + (size_t)grow * K + k0 + kc);
            As[kc + 0][row] = v.x; As[kc + 1][row] = v.y;
            As[kc + 2][row] = v.z; As[kc + 3][row] = v.w;
        }
        // B tile: 16 k x 128 n
#pragma unroll
        for (int i = 0; i < 2; i++) {
            int id  = tid + i * 256;
            int row = id >> 5;
            int col = (id & 31) * 4;
            *(float4*)&Bs[row][col] = *(const float4*)(W + (size_t)(k0 + row) * N + bn + col);
        }
        __syncthreads();
#pragma unroll
        for (int kk = 0; kk < 16; kk++) {
            float4 a0 = *(const float4*)&As[kk][ty * 8];
            float4 a1 = *(const float4*)&As[kk][ty * 8 + 4];
            float4 b0 = *(const float4*)&Bs[kk][tx * 8];
            float4 b1 = *(const float4*)&Bs[kk][tx * 8 + 4];
            float a[8] = {a0.x, a0.y, a0.z, a0.w, a1.x, a1.y, a1.z, a1.w};
            float b[8] = {b0.x, b0.y, b0.z, b0.w, b1.x, b1.y, b1.z, b1.w};
#pragma unroll
            for (int i = 0; i < 8; i++)
#pragma unroll
                for (int j = 0; j < 8; j++)
                    acc[i][j] += a[i] * b[j];
        }
        __syncthreads();
    }

    float bi[8];
#pragma unroll
    for (int j = 0; j < 8; j++) bi[j] = bias[bn + tx * 8 + j];
    float sk = 0.f;
    if (act == 2) sk = 1.f / (1.f + __expf(-skipv[0]));

#pragma unroll
    for (int i = 0; i < 8; i++) {
        int row = bm + ty * 8 + i;
        if (row >= M) continue;
        int col0 = bn + tx * 8;
        float o[8];
#pragma unroll
        for (int j = 0; j < 8; j++) {
            float v = acc[i][j] + bi[j];
            if (act == 1) v = fmaxf(v, 0.f);
            o[j] = v;
        }
        if (act == 2) {
            float4 x0 = *(const float4*)(xold + (size_t)row * N + col0);
            float4 x1 = *(const float4*)(xold + (size_t)row * N + col0 + 4);
            o[0] = sk * o[0] + (1.f - sk) * x0.x; o[1] = sk * o[1] + (1.f - sk) * x0.y;
            o[2] = sk * o[2] + (1.f - sk) * x0.z; o[3] = sk * o[3] + (1.f - sk) * x0.w;
            o[4] = sk * o[4] + (1.f - sk) * x1.x; o[5] = sk * o[5] + (1.f - sk) * x1.y;
            o[6] = sk * o[6] + (1.f - sk) * x1.z; o[7] = sk * o[7] + (1.f - sk) * x1.w;
        }
        *(float4*)(C + (size_t)row * N + col0)     = make_float4(o[0], o[1], o[2], o[3]);
        *(float4*)(C + (size_t)row * N + col0 + 4) = make_float4(o[4], o[5], o[6], o[7]);
    }
}

// ------------- per-relation per-head transform: out[n,h,e] = sum_d in[n,h,d]*A[h,d,e]
__global__ void rel_transform(const float* __restrict__ kqv, int koff,
                              const float* __restrict__ A8,
                              float* __restrict__ out, int N)
{
    __shared__ float sA[2048];
    __shared__ float sv[128];
    for (int i = threadIdx.x; i < 2048; i += 128) sA[i] = A8[i];
    __syncthreads();
    const int h = threadIdx.x >> 4;
    const int e = threadIdx.x & 15;
    for (int n = blockIdx.x; n < N; n += gridDim.x) {
        sv[threadIdx.x] = kqv[(size_t)n * 384 + koff + threadIdx.x];
        __syncthreads();
        float acc = 0.f;
#pragma unroll
        for (int d = 0; d < 16; d++)
            acc += sv[h * 16 + d] * sA[(h * 16 + d) * 16 + e];
        out[(size_t)n * 128 + threadIdx.x] = acc;
        __syncthreads();
    }
}

// ---------------- CSR build ----------------
__global__ void hist_kernel(const int* __restrict__ dst, int* __restrict__ deg, int E)
{
    int i = blockIdx.x * blockDim.x + threadIdx.x;
    if (i < E) atomicAdd(&deg[dst[i]], 1);
}

// per-block exclusive scan of 1024 elements (256 threads x 4), writes block sums
__global__ void scan_partial(const int* __restrict__ deg, int* __restrict__ row,
                             int* __restrict__ bsums, int n)
{
    __shared__ int warpsum[8];
    int t = threadIdx.x;
    int lane = t & 31, wid = t >> 5;
    int base = blockIdx.x * 1024 + t * 4;
    int v0 = (base + 0 < n) ? deg[base + 0] : 0;
    int v1 = (base + 1 < n) ? deg[base + 1] : 0;
    int v2 = (base + 2 < n) ? deg[base + 2] : 0;
    int v3 = (base + 3 < n) ? deg[base + 3] : 0;
    int e0 = 0, e1 = v0, e2 = e1 + v1, e3 = e2 + v2;
    int tot = e3 + v3;
    int inc = tot;
#pragma unroll
    for (int off = 1; off < 32; off <<= 1) {
        int y = __shfl_up_sync(0xffffffffu, inc, off);
        if (lane >= off) inc += y;
    }
    if (lane == 31) warpsum[wid] = inc;
    __syncthreads();
    if (wid == 0) {
        int w = (lane < 8) ? warpsum[lane] : 0;
#pragma unroll
        for (int off = 1; off < 8; off <<= 1) {
            int y = __shfl_up_sync(0xffffffffu, w, off);
            if (lane >= off) w += y;
        }
        if (lane < 8) warpsum[lane] = w;
    }
    __syncthreads();
    int warpExcl = (wid == 0) ? 0 : warpsum[wid - 1];
    int thrExcl = warpExcl + inc - tot;
    if (base + 0 < n) row[base + 0] = thrExcl + e0;
    if (base + 1 < n) row[base + 1] = thrExcl + e1;
    if (base + 2 < n) row[base + 2] = thrExcl + e2;
    if (base + 3 < n) row[base + 3] = thrExcl + e3;
    if (t == 0) bsums[blockIdx.x] = warpsum[7];
}

// exclusive scan of <=256 block sums in one block; writes total at bsums[nb]
__global__ void scan_small(int* __restrict__ bsums, int nb)
{
    __shared__ int warpsum[8];
    int t = threadIdx.x;
    int lane = t & 31, wid = t >> 5;
    int v = (t < nb) ? bsums[t] : 0;
    int inc = v;
#pragma unroll
    for (int off = 1; off < 32; off <<= 1) {
        int y = __shfl_up_sync(0xffffffffu, inc, off);
        if (lane >= off) inc += y;
    }
    if (lane == 31) warpsum[wid] = inc;
    __syncthreads();
    if (wid == 0) {
        int w = (lane < 8) ? warpsum[lane] : 0;
#pragma unroll
        for (int off = 1; off < 8; off <<= 1) {
            int y = __shfl_up_sync(0xffffffffu, w, off);
            if (lane >= off) w += y;
        }
        if (lane < 8) warpsum[lane] = w;
    }
    __syncthreads();
    int warpExcl = (wid == 0) ? 0 : warpsum[wid - 1];
    int excl = warpExcl + inc - v;
    if (t < nb) bsums[t] = excl;
    if (t == 255) bsums[nb] = warpExcl + inc;   // grand total
}

// add block offsets, init cursor copy, write row[n]=total
__global__ void add_off(int* __restrict__ row, int* __restrict__ cur,
                        const int* __restrict__ bsums, int n, int nb)
{
    int i = blockIdx.x * blockDim.x + threadIdx.x;
    if (i < n) {
        int r = row[i] + bsums[i >> 10];
        row[i] = r;
        cur[i] = r;
    }
    if (i == 0) row[n] = bsums[nb];
}

__global__ void scatter_kernel(const int* __restrict__ src, const int* __restrict__ dst,
                               int* __restrict__ cursor, int* __restrict__ out,
                               int E, int srcOffset)
{
    int i = blockIdx.x * blockDim.x + threadIdx.x;
    if (i >= E) return;
    int p = atomicAdd(&cursor[dst[i]], 1);
    out[p] = src[i] + srcOffset;
}

// ---------------- fused attention + softmax + aggregate + gelu ----------------
__global__ void attn_agg(const float* __restrict__ kqv, const float* __restrict__ KE,
                         const float* __restrict__ VE,
                         const int* __restrict__ rowptr, const int* __restrict__ srccol,
                         const float* __restrict__ prelA, const float* __restrict__ prelB,
                         int relBoundary, float* __restrict__ agg, int N)
{
    int warp = (blockIdx.x * blockDim.x + threadIdx.x) >> 5;
    int lane = threadIdx.x & 31;
    if (warp >= N) return;
    int h = lane >> 2;
    int c = h * 16 + (lane & 3) * 4;
    float4 q4 = *(const float4*)(kqv + (size_t)warp * 384 + 128 + c);
    float pA = prelA[h] * 0.25f;
    float pB = prelB[h] * 0.25f;
    int js = rowptr[warp], je = rowptr[warp + 1];
    float m = -INFINITY, s = 0.f;
    float4 acc = make_float4(0.f, 0.f, 0.f, 0.f);
    for (int j = js; j < je; j++) {
        int sr = srccol[j];
        float4 k4 = *(const float4*)(KE + (size_t)sr * 128 + c);
        float part = q4.x * k4.x + q4.y * k4.y + q4.z * k4.z + q4.w * k4.w;
        part += __shfl_xor_sync(0xffffffffu, part, 1);
        part += __shfl_xor_sync(0xffffffffu, part, 2);
        float a = part * ((sr >= relBoundary) ? pB : pA);
        float newm = fmaxf(m, a);
        float scl = __expf(m - newm);
        float w = __expf(a - newm);
        s = s * scl + w;
        float4 v4 = *(const float4*)(VE + (size_t)sr * 128 + c);
        acc.x = acc.x * scl + w * v4.x;
        acc.y = acc.y * scl + w * v4.y;
        acc.z = acc.z * scl + w * v4.z;
        acc.w = acc.w * scl + w * v4.w;
        m = newm;
    }
    float inv = 1.f / (s + 1e-16f);
    float4 r;
    float v;
    v = acc.x * inv; r.x = 0.5f * v * (1.f + erff(v * 0.70710678118654752f));
    v = acc.y * inv; r.y = 0.5f * v * (1.f + erff(v * 0.70710678118654752f));
    v = acc.z * inv; r.z = 0.5f * v * (1.f + erff(v * 0.70710678118654752f));
    v = acc.w * inv; r.w = 0.5f * v * (1.f + erff(v * 0.70710678118654752f));
    *(float4*)(agg + (size_t)warp * 128 + c) = r;
}

// ---------------- BatchNorm ----------------
__global__ void bn_stats(const float* __restrict__ h, float* __restrict__ stats, int N)
{
    int c = threadIdx.x;
    int r0 = blockIdx.x * 256;
    int r1 = min(N, r0 + 256);
    float s = 0.f, s2 = 0.f;
    for (int r = r0; r < r1; r++) {
        float v = h[(size_t)r * 128 + c];
        s += v; s2 += v * v;
    }
    atomicAdd(&stats[c], s);
    atomicAdd(&stats[128 + c], s2);
}

__global__ void bn_apply(const float* __restrict__ h, const float* __restrict__ stats,
                         const float* __restrict__ gamma, const float* __restrict__ beta,
                         float* __restrict__ out, int N)
{
    int i = blockIdx.x * blockDim.x + threadIdx.x;
    if (i >= N * 128) return;
    int c = i & 127;
    float invN = 1.f / (float)N;
    float mu = stats[c] * invN;
    float var = stats[128 + c] * invN - mu * mu;
    float v = h[i];
    out[i] = (v - mu) * rsqrtf(var + BN_EPS) * gamma[c] + beta[c];
}

// ---------------------------------------------------------------
static inline int cdiv(long long a, long long b) { return (int)((a + b - 1) / b); }

extern "C" void kernel_launch(void* const* d_in, const int* in_sizes, int n_in,
                              void* d_out, int out_size)
{
    const float* x_author = (const float*)d_in[0];
    const float* x_paper  = (const float*)d_in[1];
    const int* writes_src = (const int*)d_in[2];
    const int* writes_dst = (const int*)d_in[3];
    const int* rev_src    = (const int*)d_in[4];
    const int* rev_dst    = (const int*)d_in[5];
    const int* cites_src  = (const int*)d_in[6];
    const int* cites_dst  = (const int*)d_in[7];
    const float* linA_W   = (const float*)d_in[8];
    const float* linA_b   = (const float*)d_in[9];
    const float* linP_W   = (const float*)d_in[10];
    const float* linP_b   = (const float*)d_in[11];
    const float* kqv_W    = (const float*)d_in[12];
    const float* kqv_b    = (const float*)d_in[13];
    const float* a_k      = (const float*)d_in[14];
    const float* a_v      = (const float*)d_in[15];
    const float* p_rel    = (const float*)d_in[16];
    const float* out_W    = (const float*)d_in[17];
    const float* out_b    = (const float*)d_in[18];
    const float* skipP    = (const float*)d_in[19];
    const float* bn_gamma = (const float*)d_in[20];
    const float* bn_beta  = (const float*)d_in[21];

    float* base = nullptr;
    cudaGetSymbolAddress((void**)&base, g_scratch);

    float* XA   = base + OFF_XA;
    float* XP   = base + OFF_XP;
    float* KQVA = base + OFF_KQVA;
    float* KQVP = base + OFF_KQVP;
    float* KEP  = base + OFF_KEP;
    float* VEP  = base + OFF_VEP;
    float* KEA  = base + OFF_KEA;
    float* VEA  = base + OFF_VEA;
    float* AGGA = base + OFF_AGGA;
    float* AGGP = base + OFF_AGGP;
    float* TMPA = base + OFF_TMPA;
    float* TMPP = base + OFF_TMPP;
    float* STA  = base + OFF_STATS;
    float* STP  = base + OFF_STATS + 256;
    int* ibase  = (int*)(base + OFF_INT);
    int* ROWP   = ibase + IOFF_ROWP;
    int* ROWA   = ibase + IOFF_ROWA;
    int* CURP   = ibase + IOFF_CURP;
    int* CURA   = ibase + IOFF_CURA;
    int* SRCP   = ibase + IOFF_SRCP;
    int* SRCA   = ibase + IOFF_SRCA;
    int* BS     = ibase + IOFF_BS;

    // -------- CSR build (once per launch) --------
    const int nbP = cdiv(NP, 1024), nbA = cdiv(NA, 1024);
    cudaMemsetAsync(CURP, 0, (size_t)NP * 4, 0);
    cudaMemsetAsync(CURA, 0, (size_t)NA * 4, 0);
    hist_kernel<<<cdiv(EW, 256), 256>>>(writes_dst, CURP, EW);
    hist_kernel<<<cdiv(EC, 256), 256>>>(cites_dst, CURP, EC);
    hist_kernel<<<cdiv(ER, 256), 256>>>(rev_dst, CURA, ER);
    scan_partial<<<nbP, 256>>>(CURP, ROWP, BS, NP);
    scan_small<<<1, 256>>>(BS, nbP);
    add_off<<<cdiv(NP, 256), 256>>>(ROWP, CURP, BS, NP, nbP);
    scan_partial<<<nbA, 256>>>(CURA, ROWA, BS, NA);
    scan_small<<<1, 256>>>(BS, nbA);
    add_off<<<cdiv(NA, 256), 256>>>(ROWA, CURA, BS, NA, nbA);
    scatter_kernel<<<cdiv(EW, 256), 256>>>(writes_src, writes_dst, CURP, SRCP, EW, 0);
    scatter_kernel<<<cdiv(EC, 256), 256>>>(cites_src, cites_dst, CURP, SRCP, EC, NA);
    scatter_kernel<<<cdiv(ER, 256), 256>>>(rev_src, rev_dst, CURA, SRCA, ER, 0);

    // -------- input projections + relu --------
    gemm128<<<dim3(1, cdiv(NA, 128)), 256>>>(x_author, linA_W, linA_b, XA, NA, 128, 128, 1, nullptr, nullptr);
    gemm128<<<dim3(1, cdiv(NP, 128)), 256>>>(x_paper,  linP_W, linP_b, XP, NP, 128, 128, 1, nullptr, nullptr);

    for (int l = 0; l < 2; l++) {
        // KQV GEMMs
        gemm128<<<dim3(3, cdiv(NA, 128)), 256>>>(XA, kqv_W + (size_t)(l * 2 + 0) * 128 * 384,
                                                 kqv_b + (size_t)(l * 2 + 0) * 384, KQVA, NA, 384, 128, 0, nullptr, nullptr);
        gemm128<<<dim3(3, cdiv(NP, 128)), 256>>>(XP, kqv_W + (size_t)(l * 2 + 1) * 128 * 384,
                                                 kqv_b + (size_t)(l * 2 + 1) * 384, KQVP, NP, 384, 128, 0, nullptr, nullptr);

        // per-relation K/V transforms into combined source tables
        rel_transform<<<2048, 128>>>(KQVA, 0,   a_k + (size_t)(l * 3 + 0) * 2048, KEP, NA);
        rel_transform<<<2048, 128>>>(KQVA, 256, a_v + (size_t)(l * 3 + 0) * 2048, VEP, NA);
        rel_transform<<<2048, 128>>>(KQVP, 0,   a_k + (size_t)(l * 3 + 2) * 2048, KEP + (size_t)NA * 128, NP);
        rel_transform<<<2048, 128>>>(KQVP, 256, a_v + (size_t)(l * 3 + 2) * 2048, VEP + (size_t)NA * 128, NP);
        rel_transform<<<2048, 128>>>(KQVP, 0,   a_k + (size_t)(l * 3 + 1) * 2048, KEA, NP);
        rel_transform<<<2048, 128>>>(KQVP, 256, a_v + (size_t)(l * 3 + 1) * 2048, VEA, NP);

        // fused attention + softmax + aggregation + gelu
        attn_agg<<<cdiv((long long)NP * 32, 256), 256>>>(KQVP, KEP, VEP, ROWP, SRCP,
                                                         p_rel + (size_t)(l * 3 + 0) * NH,
                                                         p_rel + (size_t)(l * 3 + 2) * NH,
                                                         NA, AGGP, NP);
        attn_agg<<<cdiv((long long)NA * 32, 256), 256>>>(KQVA, KEA, VEA, ROWA, SRCA,
                                                         p_rel + (size_t)(l * 3 + 1) * NH,
                                                         p_rel + (size_t)(l * 3 + 1) * NH,
                                                         NP + 1, AGGA, NA);

        // output projection + fused sigmoid-skip mix
        gemm128<<<dim3(1, cdiv(NA, 128)), 256>>>(AGGA, out_W + (size_t)(l * 2 + 0) * 128 * 128,
                                                 out_b + (size_t)(l * 2 + 0) * 128, TMPA, NA, 128, 128, 2,
                                                 XA, skipP + (l * 2 + 0));
        gemm128<<<dim3(1, cdiv(NP, 128)), 256>>>(AGGP, out_W + (size_t)(l * 2 + 1) * 128 * 128,
                                                 out_b + (size_t)(l * 2 + 1) * 128, TMPP, NP, 128, 128, 2,
                                                 XP, skipP + (l * 2 + 1));

        // batch norm (training-mode stats), per node type
        cudaMemsetAsync(STA, 0, 512 * 4, 0);
        bn_stats<<<cdiv(NA, 256), 128>>>(TMPA, STA, NA);
        bn_stats<<<cdiv(NP, 256), 128>>>(TMPP, STP, NP);
        float* outA = (l == 1) ? (float*)d_out : XA;
        float* outP = (l == 1) ? (float*)d_out + (size_t)NA * 128 : XP;
        bn_apply<<<cdiv((long long)NA * 128, 256), 256>>>(TMPA, STA, bn_gamma + (size_t)l * 128,
                                                          bn_beta + (size_t)l * 128, outA, NA);
        bn_apply<<<cdiv((long long)NP * 128, 256), 256>>>(TMPP, STP, bn_gamma + (size_t)l * 128,
                                                          bn_beta + (size_t)l * 128, outP, NP);
    }
}

// round 4
// speedup vs baseline: 2.4268x; 1.3795x over previous
#include <cuda_runtime.h>
#include <math.h>
#include <stdint.h>

// ---------------- problem sizes ----------------
#define NA 50000
#define NP 100000
#define HC 128
#define NH 8
#define EW 400000
#define ER 400000
#define EC 800000
#define EP (EW + EC)
#define BN_EPS 1e-5f

// ---------------- scratch layout (floats) ----------------
#define OFF_XA    0ull
#define OFF_XP    (OFF_XA   + (size_t)NA*128)
#define OFF_KQVA  (OFF_XP   + (size_t)NP*128)
#define OFF_KQVP  (OFF_KQVA + (size_t)NA*384)
#define OFF_KEP   (OFF_KQVP + (size_t)NP*384)        // [(NA+NP),128]
#define OFF_VEP   (OFF_KEP  + (size_t)(NA+NP)*128)
#define OFF_KEA   (OFF_VEP  + (size_t)(NA+NP)*128)   // [NP,128]
#define OFF_VEA   (OFF_KEA  + (size_t)NP*128)
#define OFF_AGGA  (OFF_VEA  + (size_t)NP*128)
#define OFF_AGGP  (OFF_AGGA + (size_t)NA*128)
#define OFF_TMPA  (OFF_AGGP + (size_t)NP*128)
#define OFF_TMPP  (OFF_TMPA + (size_t)NA*128)
#define OFF_STATS (OFF_TMPP + (size_t)NP*128)
// integer region (reinterpreted as int*)
#define OFF_INT   (OFF_STATS + 512ull)
#define IOFF_ROWP 0ull                         // NP+1
#define IOFF_ROWA (IOFF_ROWP + NP + 1)         // NA+1
#define IOFF_CURP (IOFF_ROWA + NA + 1)         // NP
#define IOFF_CURA (IOFF_CURP + NP)             // NA
#define IOFF_SRCP (IOFF_CURA + NA)             // EP
#define IOFF_SRCA (IOFF_SRCP + EP)             // ER
#define IOFF_BS   (IOFF_SRCA + ER)             // 256 (block sums)
#define INT_TOTAL (IOFF_BS + 256)
#define TOTAL_FLOATS (OFF_INT + INT_TOTAL + 64ull)

__device__ float g_scratch[TOTAL_FLOATS];

// ---------------- tf32 helpers ----------------
__device__ __forceinline__ uint32_t f2tf32(float x)
{
    uint32_t r;
    asm("cvt.rna.tf32.f32 %0, %1;" : "=r"(r) : "f"(x));
    return r;
}

__device__ __forceinline__ void mma_tf32(float4& c, const uint32_t* a, const uint32_t* b)
{
    asm volatile(
        "mma.sync.aligned.m16n8k8.row.col.f32.tf32.tf32.f32 "
        "{%0,%1,%2,%3}, {%4,%5,%6,%7}, {%8,%9}, {%0,%1,%2,%3};"
        : "+f"(c.x), "+f"(c.y), "+f"(c.z), "+f"(c.w)
        : "r"(a[0]), "r"(a[1]), "r"(a[2]), "r"(a[3]), "r"(b[0]), "r"(b[1]));
}

// ---------------- tf32 tensor-core GEMM ----------------
// C[M,N] = A[M,K] @ W[K,N] + bias. BM=128, BN=128, BK=16, 256 threads (8 warps 2x4).
// Warp tile 64x32 (4 m-frags x 4 n-frags of m16n8k8).
// act: 0=none, 1=relu, 2=skip-mix (v = sk*v + (1-sk)*xold)
__global__ void __launch_bounds__(256)
gemm_tf32(const float* __restrict__ A, const float* __restrict__ W,
          const float* __restrict__ bias, float* __restrict__ C,
          int M, int N, int K, int act,
          const float* __restrict__ xold, const float* __restrict__ skipv)
{
    __shared__ uint32_t As[128][20];   // [row][k], pad 20 -> conflict-free frag loads
    __shared__ uint32_t Bs[16][136];   // [k][n],  pad 136 -> conflict-free frag loads

    const int bm = blockIdx.y * 128;
    const int bn = blockIdx.x * 128;
    const int tid = threadIdx.x;
    const int lane = tid & 31;
    const int warp = tid >> 5;
    const int wm = warp >> 2;          // 0..1
    const int wn = warp & 3;           // 0..3

    float4 acc[4][4];
#pragma unroll
    for (int i = 0; i < 4; i++)
#pragma unroll
        for (int j = 0; j < 4; j++) acc[i][j] = make_float4(0.f, 0.f, 0.f, 0.f);

    for (int k0 = 0; k0 < K; k0 += 16) {
        // A tile: 128 rows x 16 k
#pragma unroll
        for (int i = 0; i < 2; i++) {
            int id  = tid + i * 256;
            int row = id >> 2;
            int kc  = (id & 3) * 4;
            int grow = bm + row;
            float4 v = make_float4(0.f, 0.f, 0.f, 0.f);
            if (grow < M) v = *(const float4*)(A + (size_t)grow * K + k0 + kc);
            As[row][kc + 0] = f2tf32(v.x); As[row][kc + 1] = f2tf32(v.y);
            As[row][kc + 2] = f2tf32(v.z); As[row][kc + 3] = f2tf32(v.w);
        }
        // B tile: 16 k x 128 n
#pragma unroll
        for (int i = 0; i < 2; i++) {
            int id  = tid + i * 256;
            int row = id >> 5;
            int col = (id & 31) * 4;
            float4 v = *(const float4*)(W + (size_t)(k0 + row) * N + bn + col);
            Bs[row][col + 0] = f2tf32(v.x); Bs[row][col + 1] = f2tf32(v.y);
            Bs[row][col + 2] = f2tf32(v.z); Bs[row][col + 3] = f2tf32(v.w);
        }
        __syncthreads();

#pragma unroll
        for (int ks = 0; ks < 16; ks += 8) {
            uint32_t af[4][4];
            const int kc = ks + (lane & 3);
#pragma unroll
            for (int mf = 0; mf < 4; mf++) {
                int r = wm * 64 + mf * 16 + (lane >> 2);
                af[mf][0] = As[r][kc];
                af[mf][1] = As[r + 8][kc];
                af[mf][2] = As[r][kc + 4];
                af[mf][3] = As[r + 8][kc + 4];
            }
            uint32_t bf[4][2];
#pragma unroll
            for (int nf = 0; nf < 4; nf++) {
                int n = wn * 32 + nf * 8 + (lane >> 2);
                bf[nf][0] = Bs[kc][n];
                bf[nf][1] = Bs[kc + 4][n];
            }
#pragma unroll
            for (int mf = 0; mf < 4; mf++)
#pragma unroll
                for (int nf = 0; nf < 4; nf++)
                    mma_tf32(acc[mf][nf], af[mf], bf[nf]);
        }
        __syncthreads();
    }

    // epilogue
    const int lr = lane >> 2;
    const int lc = (lane & 3) * 2;
    float sk = 0.f;
    if (act == 2) sk = 1.f / (1.f + __expf(-skipv[0]));
    float2 bv[4];
#pragma unroll
    for (int nf = 0; nf < 4; nf++) {
        int c0 = bn + wn * 32 + nf * 8 + lc;
        bv[nf] = *(const float2*)(bias + c0);
    }
#pragma unroll
    for (int mf = 0; mf < 4; mf++) {
        int r0 = bm + wm * 64 + mf * 16 + lr;
        int r1 = r0 + 8;
#pragma unroll
        for (int nf = 0; nf < 4; nf++) {
            int c0 = bn + wn * 32 + nf * 8 + lc;
            float4 a = acc[mf][nf];
            float2 o0 = make_float2(a.x + bv[nf].x, a.y + bv[nf].y);
            float2 o1 = make_float2(a.z + bv[nf].x, a.w + bv[nf].y);
            if (act == 1) {
                o0.x = fmaxf(o0.x, 0.f); o0.y = fmaxf(o0.y, 0.f);
                o1.x = fmaxf(o1.x, 0.f); o1.y = fmaxf(o1.y, 0.f);
            } else if (act == 2) {
                if (r0 < M) {
                    float2 x0 = *(const float2*)(xold + (size_t)r0 * N + c0);
                    o0.x = sk * o0.x + (1.f - sk) * x0.x;
                    o0.y = sk * o0.y + (1.f - sk) * x0.y;
                }
                if (r1 < M) {
                    float2 x1 = *(const float2*)(xold + (size_t)r1 * N + c0);
                    o1.x = sk * o1.x + (1.f - sk) * x1.x;
                    o1.y = sk * o1.y + (1.f - sk) * x1.y;
                }
            }
            if (r0 < M) *(float2*)(C + (size_t)r0 * N + c0) = o0;
            if (r1 < M) *(float2*)(C + (size_t)r1 * N + c0) = o1;
        }
    }
}

// ------------- fused per-relation per-head K+V transform -------------
// outK[n,h,e] = sum_d k[n,h,d]*Ak[h,d,e] ; outV likewise from v-slice.
__global__ void rel_transform_kv(const float* __restrict__ kqv,
                                 const float* __restrict__ Ak, const float* __restrict__ Av,
                                 float* __restrict__ outK, float* __restrict__ outV, int N)
{
    __shared__ float sAk[2048], sAv[2048];
    __shared__ float skk[128], svv[128];
    for (int i = threadIdx.x; i < 2048; i += 128) { sAk[i] = Ak[i]; sAv[i] = Av[i]; }
    __syncthreads();
    const int h = threadIdx.x >> 4;
    const int e = threadIdx.x & 15;
    for (int n = blockIdx.x; n < N; n += gridDim.x) {
        skk[threadIdx.x] = kqv[(size_t)n * 384 + threadIdx.x];
        svv[threadIdx.x] = kqv[(size_t)n * 384 + 256 + threadIdx.x];
        __syncthreads();
        float ak = 0.f, av = 0.f;
#pragma unroll
        for (int d = 0; d < 16; d++) {
            ak += skk[h * 16 + d] * sAk[(h * 16 + d) * 16 + e];
            av += svv[h * 16 + d] * sAv[(h * 16 + d) * 16 + e];
        }
        outK[(size_t)n * 128 + threadIdx.x] = ak;
        outV[(size_t)n * 128 + threadIdx.x] = av;
        __syncthreads();
    }
}

// ---------------- CSR build ----------------
__global__ void hist_kernel(const int* __restrict__ dst, int* __restrict__ deg, int E)
{
    int i = blockIdx.x * blockDim.x + threadIdx.x;
    if (i < E) atomicAdd(&deg[dst[i]], 1);
}

__global__ void scan_partial(const int* __restrict__ deg, int* __restrict__ row,
                             int* __restrict__ bsums, int n)
{
    __shared__ int warpsum[8];
    int t = threadIdx.x;
    int lane = t & 31, wid = t >> 5;
    int base = blockIdx.x * 1024 + t * 4;
    int v0 = (base + 0 < n) ? deg[base + 0] : 0;
    int v1 = (base + 1 < n) ? deg[base + 1] : 0;
    int v2 = (base + 2 < n) ? deg[base + 2] : 0;
    int v3 = (base + 3 < n) ? deg[base + 3] : 0;
    int e0 = 0, e1 = v0, e2 = e1 + v1, e3 = e2 + v2;
    int tot = e3 + v3;
    int inc = tot;
#pragma unroll
    for (int off = 1; off < 32; off <<= 1) {
        int y = __shfl_up_sync(0xffffffffu, inc, off);
        if (lane >= off) inc += y;
    }
    if (lane == 31) warpsum[wid] = inc;
    __syncthreads();
    if (wid == 0) {
        int w = (lane < 8) ? warpsum[lane] : 0;
#pragma unroll
        for (int off = 1; off < 8; off <<= 1) {
            int y = __shfl_up_sync(0xffffffffu, w, off);
            if (lane >= off) w += y;
        }
        if (lane < 8) warpsum[lane] = w;
    }
    __syncthreads();
    int warpExcl = (wid == 0) ? 0 : warpsum[wid - 1];
    int thrExcl = warpExcl + inc - tot;
    if (base + 0 < n) row[base + 0] = thrExcl + e0;
    if (base + 1 < n) row[base + 1] = thrExcl + e1;
    if (base + 2 < n) row[base + 2] = thrExcl + e2;
    if (base + 3 < n) row[base + 3] = thrExcl + e3;
    if (t == 0) bsums[blockIdx.x] = warpsum[7];
}

__global__ void scan_small(int* __restrict__ bsums, int nb)
{
    __shared__ int warpsum[8];
    int t = threadIdx.x;
    int lane = t & 31, wid = t >> 5;
    int v = (t < nb) ? bsums[t] : 0;
    int inc = v;
#pragma unroll
    for (int off = 1; off < 32; off <<= 1) {
        int y = __shfl_up_sync(0xffffffffu, inc, off);
        if (lane >= off) inc += y;
    }
    if (lane == 31) warpsum[wid] = inc;
    __syncthreads();
    if (wid == 0) {
        int w = (lane < 8) ? warpsum[lane] : 0;
#pragma unroll
        for (int off = 1; off < 8; off <<= 1) {
            int y = __shfl_up_sync(0xffffffffu, w, off);
            if (lane >= off) w += y;
        }
        if (lane < 8) warpsum[lane] = w;
    }
    __syncthreads();
    int warpExcl = (wid == 0) ? 0 : warpsum[wid - 1];
    int excl = warpExcl + inc - v;
    if (t < nb) bsums[t] = excl;
    if (t == 255) bsums[nb] = warpExcl + inc;
}

__global__ void add_off(int* __restrict__ row, int* __restrict__ cur,
                        const int* __restrict__ bsums, int n, int nb)
{
    int i = blockIdx.x * blockDim.x + threadIdx.x;
    if (i < n) {
        int r = row[i] + bsums[i >> 10];
        row[i] = r;
        cur[i] = r;
    }
    if (i == 0) row[n] = bsums[nb];
}

__global__ void scatter_kernel(const int* __restrict__ src, const int* __restrict__ dst,
                               int* __restrict__ cursor, int* __restrict__ out,
                               int E, int srcOffset)
{
    int i = blockIdx.x * blockDim.x + threadIdx.x;
    if (i >= E) return;
    int p = atomicAdd(&cursor[dst[i]], 1);
    out[p] = src[i] + srcOffset;
}

// ---------------- fused attention + softmax + aggregate + gelu ----------------
__global__ void attn_agg(const float* __restrict__ kqv, const float* __restrict__ KE,
                         const float* __restrict__ VE,
                         const int* __restrict__ rowptr, const int* __restrict__ srccol,
                         const float* __restrict__ prelA, const float* __restrict__ prelB,
                         int relBoundary, float* __restrict__ agg, int N)
{
    int warp = (blockIdx.x * blockDim.x + threadIdx.x) >> 5;
    int lane = threadIdx.x & 31;
    if (warp >= N) return;
    int h = lane >> 2;
    int c = h * 16 + (lane & 3) * 4;
    float4 q4 = *(const float4*)(kqv + (size_t)warp * 384 + 128 + c);
    float pA = prelA[h] * 0.25f;
    float pB = prelB[h] * 0.25f;
    int js = rowptr[warp], je = rowptr[warp + 1];
    float m = -INFINITY, s = 0.f;
    float4 acc = make_float4(0.f, 0.f, 0.f, 0.f);
    for (int j = js; j < je; j++) {
        int sr = srccol[j];
        float4 k4 = *(const float4*)(KE + (size_t)sr * 128 + c);
        float part = q4.x * k4.x + q4.y * k4.y + q4.z * k4.z + q4.w * k4.w;
        part += __shfl_xor_sync(0xffffffffu, part, 1);
        part += __shfl_xor_sync(0xffffffffu, part, 2);
        float a = part * ((sr >= relBoundary) ? pB : pA);
        float newm = fmaxf(m, a);
        float scl = __expf(m - newm);
        float w = __expf(a - newm);
        s = s * scl + w;
        float4 v4 = *(const float4*)(VE + (size_t)sr * 128 + c);
        acc.x = acc.x * scl + w * v4.x;
        acc.y = acc.y * scl + w * v4.y;
        acc.z = acc.z * scl + w * v4.z;
        acc.w = acc.w * scl + w * v4.w;
        m = newm;
    }
    float inv = 1.f / (s + 1e-16f);
    float4 r;
    float v;
    v = acc.x * inv; r.x = 0.5f * v * (1.f + erff(v * 0.70710678118654752f));
    v = acc.y * inv; r.y = 0.5f * v * (1.f + erff(v * 0.70710678118654752f));
    v = acc.z * inv; r.z = 0.5f * v * (1.f + erff(v * 0.70710678118654752f));
    v = acc.w * inv; r.w = 0.5f * v * (1.f + erff(v * 0.70710678118654752f));
    *(float4*)(agg + (size_t)warp * 128 + c) = r;
}

// ---------------- BatchNorm ----------------
__global__ void bn_stats(const float* __restrict__ h, float* __restrict__ stats, int N)
{
    int c = threadIdx.x;
    int r0 = blockIdx.x * 256;
    int r1 = min(N, r0 + 256);
    float s = 0.f, s2 = 0.f;
    for (int r = r0; r < r1; r++) {
        float v = h[(size_t)r * 128 + c];
        s += v; s2 += v * v;
    }
    atomicAdd(&stats[c], s);
    atomicAdd(&stats[128 + c], s2);
}

__global__ void bn_apply(const float* __restrict__ h, const float* __restrict__ stats,
                         const float* __restrict__ gamma, const float* __restrict__ beta,
                         float* __restrict__ out, int N)
{
    int i = blockIdx.x * blockDim.x + threadIdx.x;
    if (i >= N * 128) return;
    int c = i & 127;
    float invN = 1.f / (float)N;
    float mu = stats[c] * invN;
    float var = stats[128 + c] * invN - mu * mu;
    float v = h[i];
    out[i] = (v - mu) * rsqrtf(var + BN_EPS) * gamma[c] + beta[c];
}

// ---------------------------------------------------------------
static inline int cdiv(long long a, long long b) { return (int)((a + b - 1) / b); }

extern "C" void kernel_launch(void* const* d_in, const int* in_sizes, int n_in,
                              void* d_out, int out_size)
{
    const float* x_author = (const float*)d_in[0];
    const float* x_paper  = (const float*)d_in[1];
    const int* writes_src = (const int*)d_in[2];
    const int* writes_dst = (const int*)d_in[3];
    const int* rev_src    = (const int*)d_in[4];
    const int* rev_dst    = (const int*)d_in[5];
    const int* cites_src  = (const int*)d_in[6];
    const int* cites_dst  = (const int*)d_in[7];
    const float* linA_W   = (const float*)d_in[8];
    const float* linA_b   = (const float*)d_in[9];
    const float* linP_W   = (const float*)d_in[10];
    const float* linP_b   = (const float*)d_in[11];
    const float* kqv_W    = (const float*)d_in[12];
    const float* kqv_b    = (const float*)d_in[13];
    const float* a_k      = (const float*)d_in[14];
    const float* a_v      = (const float*)d_in[15];
    const float* p_rel    = (const float*)d_in[16];
    const float* out_W    = (const float*)d_in[17];
    const float* out_b    = (const float*)d_in[18];
    const float* skipP    = (const float*)d_in[19];
    const float* bn_gamma = (const float*)d_in[20];
    const float* bn_beta  = (const float*)d_in[21];

    float* base = nullptr;
    cudaGetSymbolAddress((void**)&base, g_scratch);

    float* XA   = base + OFF_XA;
    float* XP   = base + OFF_XP;
    float* KQVA = base + OFF_KQVA;
    float* KQVP = base + OFF_KQVP;
    float* KEP  = base + OFF_KEP;
    float* VEP  = base + OFF_VEP;
    float* KEA  = base + OFF_KEA;
    float* VEA  = base + OFF_VEA;
    float* AGGA = base + OFF_AGGA;
    float* AGGP = base + OFF_AGGP;
    float* TMPA = base + OFF_TMPA;
    float* TMPP = base + OFF_TMPP;
    float* STA  = base + OFF_STATS;
    float* STP  = base + OFF_STATS + 256;
    int* ibase  = (int*)(base + OFF_INT);
    int* ROWP   = ibase + IOFF_ROWP;
    int* ROWA   = ibase + IOFF_ROWA;
    int* CURP   = ibase + IOFF_CURP;
    int* CURA   = ibase + IOFF_CURA;
    int* SRCP   = ibase + IOFF_SRCP;
    int* SRCA   = ibase + IOFF_SRCA;
    int* BS     = ibase + IOFF_BS;

    // -------- CSR build (once per launch) --------
    const int nbP = cdiv(NP, 1024), nbA = cdiv(NA, 1024);
    cudaMemsetAsync(CURP, 0, (size_t)NP * 4, 0);
    cudaMemsetAsync(CURA, 0, (size_t)NA * 4, 0);
    hist_kernel<<<cdiv(EW, 256), 256>>>(writes_dst, CURP, EW);
    hist_kernel<<<cdiv(EC, 256), 256>>>(cites_dst, CURP, EC);
    hist_kernel<<<cdiv(ER, 256), 256>>>(rev_dst, CURA, ER);
    scan_partial<<<nbP, 256>>>(CURP, ROWP, BS, NP);
    scan_small<<<1, 256>>>(BS, nbP);
    add_off<<<cdiv(NP, 256), 256>>>(ROWP, CURP, BS, NP, nbP);
    scan_partial<<<nbA, 256>>>(CURA, ROWA, BS, NA);
    scan_small<<<1, 256>>>(BS, nbA);
    add_off<<<cdiv(NA, 256), 256>>>(ROWA, CURA, BS, NA, nbA);
    scatter_kernel<<<cdiv(EW, 256), 256>>>(writes_src, writes_dst, CURP, SRCP, EW, 0);
    scatter_kernel<<<cdiv(EC, 256), 256>>>(cites_src, cites_dst, CURP, SRCP, EC, NA);
    scatter_kernel<<<cdiv(ER, 256), 256>>>(rev_src, rev_dst, CURA, SRCA, ER, 0);

    // -------- input projections + relu --------
    gemm_tf32<<<dim3(1, cdiv(NA, 128)), 256>>>(x_author, linA_W, linA_b, XA, NA, 128, 128, 1, nullptr, nullptr);
    gemm_tf32<<<dim3(1, cdiv(NP, 128)), 256>>>(x_paper,  linP_W, linP_b, XP, NP, 128, 128, 1, nullptr, nullptr);

    for (int l = 0; l < 2; l++) {
        // KQV GEMMs
        gemm_tf32<<<dim3(3, cdiv(NA, 128)), 256>>>(XA, kqv_W + (size_t)(l * 2 + 0) * 128 * 384,
                                                   kqv_b + (size_t)(l * 2 + 0) * 384, KQVA, NA, 384, 128, 0, nullptr, nullptr);
        gemm_tf32<<<dim3(3, cdiv(NP, 128)), 256>>>(XP, kqv_W + (size_t)(l * 2 + 1) * 128 * 384,
                                                   kqv_b + (size_t)(l * 2 + 1) * 384, KQVP, NP, 384, 128, 0, nullptr, nullptr);

        // per-relation K/V transforms into combined source tables
        rel_transform_kv<<<2048, 128>>>(KQVA, a_k + (size_t)(l * 3 + 0) * 2048,
                                        a_v + (size_t)(l * 3 + 0) * 2048, KEP, VEP, NA);
        rel_transform_kv<<<2048, 128>>>(KQVP, a_k + (size_t)(l * 3 + 2) * 2048,
                                        a_v + (size_t)(l * 3 + 2) * 2048,
                                        KEP + (size_t)NA * 128, VEP + (size_t)NA * 128, NP);
        rel_transform_kv<<<2048, 128>>>(KQVP, a_k + (size_t)(l * 3 + 1) * 2048,
                                        a_v + (size_t)(l * 3 + 1) * 2048, KEA, VEA, NP);

        // fused attention + softmax + aggregation + gelu
        attn_agg<<<cdiv((long long)NP * 32, 256), 256>>>(KQVP, KEP, VEP, ROWP, SRCP,
                                                         p_rel + (size_t)(l * 3 + 0) * NH,
                                                         p_rel + (size_t)(l * 3 + 2) * NH,
                                                         NA, AGGP, NP);
        attn_agg<<<cdiv((long long)NA * 32, 256), 256>>>(KQVA, KEA, VEA, ROWA, SRCA,
                                                         p_rel + (size_t)(l * 3 + 1) * NH,
                                                         p_rel + (size_t)(l * 3 + 1) * NH,
                                                         NP + 1, AGGA, NA);

        // output projection + fused sigmoid-skip mix
        gemm_tf32<<<dim3(1, cdiv(NA, 128)), 256>>>(AGGA, out_W + (size_t)(l * 2 + 0) * 128 * 128,
                                                   out_b + (size_t)(l * 2 + 0) * 128, TMPA, NA, 128, 128, 2,
                                                   XA, skipP + (l * 2 + 0));
        gemm_tf32<<<dim3(1, cdiv(NP, 128)), 256>>>(AGGP, out_W + (size_t)(l * 2 + 1) * 128 * 128,
                                                   out_b + (size_t)(l * 2 + 1) * 128, TMPP, NP, 128, 128, 2,
                                                   XP, skipP + (l * 2 + 1));

        // batch norm (training-mode stats), per node type
        cudaMemsetAsync(STA, 0, 512 * 4, 0);
        bn_stats<<<cdiv(NA, 256), 128>>>(TMPA, STA, NA);
        bn_stats<<<cdiv(NP, 256), 128>>>(TMPP, STP, NP);
        float* outA = (l == 1) ? (float*)d_out : XA;
        float* outP = (l == 1) ? (float*)d_out + (size_t)NA * 128 : XP;
        bn_apply<<<cdiv((long long)NA * 128, 256), 256>>>(TMPA, STA, bn_gamma + (size_t)l * 128,
                                                          bn_beta + (size_t)l * 128, outA, NA);
        bn_apply<<<cdiv((long long)NP * 128, 256), 256>>>(TMPP, STP, bn_gamma + (size_t)l * 128,
                                                          bn_beta + (size_t)l * 128, outP, NP);
    }
}